// round 1
// baseline (speedup 1.0000x reference)
#include <cuda_runtime.h>
#include <cuda_bf16.h>
#include <math.h>

// Problem constants
#define S_LEN 1024
#define BATCH 2
#define DMODEL 1024
#define HEADS 16
#define HDIM 64
#define TLEN 2048
#define FFDIM 4096
#define ROWS_X (S_LEN * BATCH)     // 2048
#define ROWS_T (TLEN * BATCH)      // 4096

// ---------------- scratch buffers (device globals; no allocation allowed) ----
__device__ float g_q [ROWS_X * DMODEL];
__device__ float g_ke[ROWS_T * DMODEL];
__device__ float g_kr[ROWS_T * DMODEL];
__device__ float g_v [ROWS_T * DMODEL];
__device__ float g_av[ROWS_X * DMODEL];
__device__ float g_t [ROWS_X * DMODEL];
__device__ float g_u [ROWS_X * DMODEL];
__device__ float g_h1[ROWS_X * FFDIM];

// ---------------- SGEMM: C[M,N] = A[M,Kd] * W[N,Kd]^T (+bias)(+relu) ---------
// BM=BN=128, BK=8, 256 threads, 8x8 microtile
__global__ void __launch_bounds__(256, 2)
sgemm_kernel(const float* __restrict__ A, const float* __restrict__ W,
             const float* __restrict__ bias, float* __restrict__ C,
             int M, int N, int Kd, int act)
{
    __shared__ float As[8][128];
    __shared__ float Bs[8][128];

    const int tid = threadIdx.x;
    const int tx = tid & 15;          // 0..15 -> n microtile
    const int ty = tid >> 4;          // 0..15 -> m microtile
    const int m0 = blockIdx.y * 128;
    const int n0 = blockIdx.x * 128;

    const int lrow = tid >> 1;        // 0..127
    const int lseg = (tid & 1) * 4;   // 0 or 4

    const float* Aptr = A + (size_t)(m0 + lrow) * Kd + lseg;
    const float* Wptr = W + (size_t)(n0 + lrow) * Kd + lseg;

    float acc[8][8];
#pragma unroll
    for (int i = 0; i < 8; i++)
#pragma unroll
        for (int j = 0; j < 8; j++) acc[i][j] = 0.f;

    for (int k0 = 0; k0 < Kd; k0 += 8) {
        float4 a4 = *(const float4*)(Aptr + k0);
        float4 w4 = *(const float4*)(Wptr + k0);
        As[lseg + 0][lrow] = a4.x; As[lseg + 1][lrow] = a4.y;
        As[lseg + 2][lrow] = a4.z; As[lseg + 3][lrow] = a4.w;
        Bs[lseg + 0][lrow] = w4.x; Bs[lseg + 1][lrow] = w4.y;
        Bs[lseg + 2][lrow] = w4.z; Bs[lseg + 3][lrow] = w4.w;
        __syncthreads();

#pragma unroll
        for (int k = 0; k < 8; k++) {
            float a[8], b[8];
            *(float4*)(a)     = *(const float4*)&As[k][ty * 8];
            *(float4*)(a + 4) = *(const float4*)&As[k][ty * 8 + 4];
            *(float4*)(b)     = *(const float4*)&Bs[k][tx * 8];
            *(float4*)(b + 4) = *(const float4*)&Bs[k][tx * 8 + 4];
#pragma unroll
            for (int i = 0; i < 8; i++)
#pragma unroll
                for (int j = 0; j < 8; j++)
                    acc[i][j] = fmaf(a[i], b[j], acc[i][j]);
        }
        __syncthreads();
    }

    float bv[8];
#pragma unroll
    for (int j = 0; j < 8; j++)
        bv[j] = bias ? bias[n0 + tx * 8 + j] : 0.f;

#pragma unroll
    for (int i = 0; i < 8; i++) {
        const int m = m0 + ty * 8 + i;
        float4 r0, r1;
        float v0[8];
#pragma unroll
        for (int j = 0; j < 8; j++) {
            float vv = acc[i][j] + bv[j];
            if (act == 1) vv = fmaxf(vv, 0.f);
            v0[j] = vv;
        }
        r0 = make_float4(v0[0], v0[1], v0[2], v0[3]);
        r1 = make_float4(v0[4], v0[5], v0[6], v0[7]);
        float4* crow = (float4*)(C + (size_t)m * N + n0 + tx * 8);
        crow[0] = r0;
        crow[1] = r1;
    }
}

// ---------------- Flash attention with fused-KK trick ------------------------
// score(s,t) = ( q_s . (ke_t + kr_t) + u.ke_t + v.kr_t ) / 8, mask t<=1024+s
// grid: (qblock 0..15, head 0..15, batch 0..1), 256 threads
#define FPAD 66
#define FLASH_SMEM ((4 * 64 * FPAD + 64 + 128) * 4)

__global__ void __launch_bounds__(256)
flash_kernel(const float* __restrict__ q, const float* __restrict__ ke,
             const float* __restrict__ kr, const float* __restrict__ v,
             const float* __restrict__ ub, const float* __restrict__ vb,
             float* __restrict__ out)
{
    extern __shared__ float sm[];
    float* Qt   = sm;                    // [64][66]  Q^T : Qt[d][s]
    float* KKt  = Qt  + 64 * FPAD;       // [64][66]  (ke+kr)^T : KKt[d][t]
    float* Vs   = KKt + 64 * FPAD;       // [64][66]  V[t][d]
    float* St   = Vs  + 64 * FPAD;       // [64][66]  P^T : St[t][s]
    float* biasT = St + 64 * FPAD;       // [64]
    float* ubs  = biasT + 64;            // [64]
    float* vbs  = ubs + 64;              // [64]

    const int qb = blockIdx.x, h = blockIdx.y, b = blockIdx.z;
    const int tid = threadIdx.x;
    const int tx = tid & 15, ty = tid >> 4;
    const int lane = tid & 31, wrp = tid >> 5;

    if (tid < 64)       ubs[tid]      = ub[h * 64 + tid];
    else if (tid < 128) vbs[tid - 64] = vb[h * 64 + (tid - 64)];

    // load Q tile transposed
#pragma unroll
    for (int it = 0; it < 4; it++) {
        int idx = tid + it * 256;
        int s = idx >> 4, d4 = (idx & 15) * 4;
        float4 qv = *(const float4*)(q + ((size_t)((qb * 64 + s) * BATCH + b)) * DMODEL + h * 64 + d4);
        Qt[(d4 + 0) * FPAD + s] = qv.x;
        Qt[(d4 + 1) * FPAD + s] = qv.y;
        Qt[(d4 + 2) * FPAD + s] = qv.z;
        Qt[(d4 + 3) * FPAD + s] = qv.w;
    }

    float m_i[4], l_i[4], O[4][4];
#pragma unroll
    for (int i = 0; i < 4; i++) {
        m_i[i] = -1e30f; l_i[i] = 0.f;
#pragma unroll
        for (int j = 0; j < 4; j++) O[i][j] = 0.f;
    }

    const int ntiles = 17 + qb;   // t covers [0, 1024 + qb*64 + 64)
    for (int tt = 0; tt < ntiles; tt++) {
        const int t0 = tt * 64;

        // load KK = ke+kr (transposed) + per-t bias  (warp wrp owns t rows wrp*8..+7)
#pragma unroll
        for (int r = 0; r < 8; r++) {
            int t = wrp * 8 + r;
            size_t base = ((size_t)((t0 + t) * BATCH + b)) * DMODEL + h * 64;
            float2 kev = *(const float2*)(ke + base + lane * 2);
            float2 krv = *(const float2*)(kr + base + lane * 2);
            KKt[(lane * 2 + 0) * FPAD + t] = kev.x + krv.x;
            KKt[(lane * 2 + 1) * FPAD + t] = kev.y + krv.y;
            float bsum = ubs[lane * 2] * kev.x + ubs[lane * 2 + 1] * kev.y
                       + vbs[lane * 2] * krv.x + vbs[lane * 2 + 1] * krv.y;
#pragma unroll
            for (int off = 16; off; off >>= 1)
                bsum += __shfl_xor_sync(0xffffffffu, bsum, off);
            if (lane == 0) biasT[t] = bsum;
        }
        // load V tile [t][d]
#pragma unroll
        for (int it = 0; it < 4; it++) {
            int idx = tid + it * 256;
            int t = idx >> 4, d4 = (idx & 15) * 4;
            float4 vv = *(const float4*)(v + ((size_t)((t0 + t) * BATCH + b)) * DMODEL + h * 64 + d4);
            Vs[t * FPAD + d4 + 0] = vv.x;
            Vs[t * FPAD + d4 + 1] = vv.y;
            Vs[t * FPAD + d4 + 2] = vv.z;
            Vs[t * FPAD + d4 + 3] = vv.w;
        }
        __syncthreads();

        // scores: sc[i][j] = sum_d Qt[d][ty*4+i] * KKt[d][tx*4+j]
        float sc[4][4];
#pragma unroll
        for (int i = 0; i < 4; i++)
#pragma unroll
            for (int j = 0; j < 4; j++) sc[i][j] = 0.f;

#pragma unroll 8
        for (int d = 0; d < 64; d++) {
            float a[4], bb[4];
            float2 qa = *(const float2*)&Qt[d * FPAD + ty * 4];
            float2 qc = *(const float2*)&Qt[d * FPAD + ty * 4 + 2];
            float2 ka = *(const float2*)&KKt[d * FPAD + tx * 4];
            float2 kc = *(const float2*)&KKt[d * FPAD + tx * 4 + 2];
            a[0] = qa.x; a[1] = qa.y; a[2] = qc.x; a[3] = qc.y;
            bb[0] = ka.x; bb[1] = ka.y; bb[2] = kc.x; bb[3] = kc.y;
#pragma unroll
            for (int i = 0; i < 4; i++)
#pragma unroll
                for (int j = 0; j < 4; j++)
                    sc[i][j] = fmaf(a[i], bb[j], sc[i][j]);
        }

        const bool diag = (tt == 16 + qb);
#pragma unroll
        for (int j = 0; j < 4; j++) {
            float bj = biasT[tx * 4 + j];
#pragma unroll
            for (int i = 0; i < 4; i++) {
                float vv = (sc[i][j] + bj) * 0.125f;
                if (diag && (tx * 4 + j) > (ty * 4 + i)) vv = -1e30f;
                sc[i][j] = vv;
            }
        }

        // online softmax (row groups = same ty across 16 tx lanes, width-16 shfl)
#pragma unroll
        for (int i = 0; i < 4; i++) {
            float mt = fmaxf(fmaxf(sc[i][0], sc[i][1]), fmaxf(sc[i][2], sc[i][3]));
#pragma unroll
            for (int off = 8; off; off >>= 1)
                mt = fmaxf(mt, __shfl_xor_sync(0xffffffffu, mt, off, 16));
            float mnew = fmaxf(m_i[i], mt);
            float c = __expf(m_i[i] - mnew);
            l_i[i] *= c;
#pragma unroll
            for (int j = 0; j < 4; j++) O[i][j] *= c;
            float ps = 0.f;
#pragma unroll
            for (int j = 0; j < 4; j++) {
                float pv = __expf(sc[i][j] - mnew);
                sc[i][j] = pv;
                ps += pv;
            }
            l_i[i] += ps;
            m_i[i] = mnew;
        }
        // write P transposed
#pragma unroll
        for (int i = 0; i < 4; i++)
#pragma unroll
            for (int j = 0; j < 4; j++)
                St[(tx * 4 + j) * FPAD + ty * 4 + i] = sc[i][j];
        __syncthreads();

        // O += P * V :  O[i][j] += sum_t St[t][ty*4+i] * Vs[t][tx*4+j]
#pragma unroll 8
        for (int t = 0; t < 64; t++) {
            float a[4], bb[4];
            float2 pa = *(const float2*)&St[t * FPAD + ty * 4];
            float2 pc = *(const float2*)&St[t * FPAD + ty * 4 + 2];
            float2 va = *(const float2*)&Vs[t * FPAD + tx * 4];
            float2 vc = *(const float2*)&Vs[t * FPAD + tx * 4 + 2];
            a[0] = pa.x; a[1] = pa.y; a[2] = pc.x; a[3] = pc.y;
            bb[0] = va.x; bb[1] = va.y; bb[2] = vc.x; bb[3] = vc.y;
#pragma unroll
            for (int i = 0; i < 4; i++)
#pragma unroll
                for (int j = 0; j < 4; j++)
                    O[i][j] = fmaf(a[i], bb[j], O[i][j]);
        }
        __syncthreads();
    }

    // finalize: reduce l over the 16-lane row group, normalize, store
#pragma unroll
    for (int i = 0; i < 4; i++) {
        float lt = l_i[i];
#pragma unroll
        for (int off = 8; off; off >>= 1)
            lt += __shfl_xor_sync(0xffffffffu, lt, off, 16);
        float inv = 1.f / lt;
        int s = qb * 64 + ty * 4 + i;
        float* orow = out + ((size_t)(s * BATCH + b)) * DMODEL + h * 64 + tx * 4;
#pragma unroll
        for (int j = 0; j < 4; j++) orow[j] = O[i][j] * inv;
    }
}

// ---------------- LayerNorm(a + res) * g + b --------------------------------
__global__ void __launch_bounds__(256)
ln_kernel(const float* __restrict__ a, const float* __restrict__ res,
          const float* __restrict__ g, const float* __restrict__ bta,
          float* __restrict__ out)
{
    const int row = blockIdx.x;
    const int tid = threadIdx.x;
    const int lane = tid & 31, wrp = tid >> 5;
    __shared__ float red[8];
    __shared__ float bc;

    float vals[4];
    float s = 0.f;
    const float* ar = a + (size_t)row * DMODEL;
    const float* rr = res + (size_t)row * DMODEL;
#pragma unroll
    for (int i = 0; i < 4; i++) {
        int d = tid + i * 256;
        vals[i] = ar[d] + rr[d];
        s += vals[i];
    }
#pragma unroll
    for (int off = 16; off; off >>= 1) s += __shfl_xor_sync(0xffffffffu, s, off);
    if (lane == 0) red[wrp] = s;
    __syncthreads();
    if (tid == 0) {
        float t = 0.f;
#pragma unroll
        for (int w = 0; w < 8; w++) t += red[w];
        bc = t * (1.f / DMODEL);
    }
    __syncthreads();
    const float mu = bc;

    float vs = 0.f;
#pragma unroll
    for (int i = 0; i < 4; i++) {
        float dd = vals[i] - mu;
        vs += dd * dd;
    }
#pragma unroll
    for (int off = 16; off; off >>= 1) vs += __shfl_xor_sync(0xffffffffu, vs, off);
    __syncthreads();
    if (lane == 0) red[wrp] = vs;
    __syncthreads();
    if (tid == 0) {
        float t = 0.f;
#pragma unroll
        for (int w = 0; w < 8; w++) t += red[w];
        bc = rsqrtf(t * (1.f / DMODEL) + 1e-5f);
    }
    __syncthreads();
    const float rstd = bc;

    float* orow = out + (size_t)row * DMODEL;
#pragma unroll
    for (int i = 0; i < 4; i++) {
        int d = tid + i * 256;
        orow[d] = (vals[i] - mu) * rstd * g[d] + bta[d];
    }
}

// ---------------- launcher ---------------------------------------------------
extern "C" void kernel_launch(void* const* d_in, const int* in_sizes, int n_in,
                              void* d_out, int out_size)
{
    const float* x      = (const float*)d_in[0];
    const float* p      = (const float*)d_in[1];
    /* mask d_in[2] is analytic (t <= 1024+s): unused */
    const float* memory = (const float*)d_in[3];
    const float* u_bias = (const float*)d_in[4];
    const float* v_bias = (const float*)d_in[5];
    const float* wq  = (const float*)d_in[6];
    const float* wke = (const float*)d_in[7];
    const float* wkr = (const float*)d_in[8];
    const float* wv  = (const float*)d_in[9];
    const float* wc  = (const float*)d_in[10];
    const float* w1  = (const float*)d_in[11];
    const float* w1b = (const float*)d_in[12];
    const float* w2  = (const float*)d_in[13];
    const float* w2b = (const float*)d_in[14];
    const float* ln1g = (const float*)d_in[15];
    const float* ln1b = (const float*)d_in[16];
    const float* ln2g = (const float*)d_in[17];
    const float* ln2b = (const float*)d_in[18];
    float* out = (float*)d_out;

    float *q, *ke, *kr, *v, *av, *tbuf, *ubuf, *h1;
    cudaGetSymbolAddress((void**)&q,    g_q);
    cudaGetSymbolAddress((void**)&ke,   g_ke);
    cudaGetSymbolAddress((void**)&kr,   g_kr);
    cudaGetSymbolAddress((void**)&v,    g_v);
    cudaGetSymbolAddress((void**)&av,   g_av);
    cudaGetSymbolAddress((void**)&tbuf, g_t);
    cudaGetSymbolAddress((void**)&ubuf, g_u);
    cudaGetSymbolAddress((void**)&h1,   g_h1);

    cudaFuncSetAttribute(flash_kernel,
                         cudaFuncAttributeMaxDynamicSharedMemorySize, FLASH_SMEM);

    const dim3 blk(256);
    const size_t half = (size_t)ROWS_X * DMODEL;   // 2048*1024

    // projections
    sgemm_kernel<<<dim3(8, 16), blk>>>(x,      wq,  nullptr, q,           ROWS_X, DMODEL, DMODEL, 0);
    sgemm_kernel<<<dim3(8, 16), blk>>>(memory, wke, nullptr, ke,          ROWS_X, DMODEL, DMODEL, 0);
    sgemm_kernel<<<dim3(8, 16), blk>>>(x,      wke, nullptr, ke + half,   ROWS_X, DMODEL, DMODEL, 0);
    sgemm_kernel<<<dim3(8, 32), blk>>>(p,      wkr, nullptr, kr,          ROWS_T, DMODEL, DMODEL, 0);
    sgemm_kernel<<<dim3(8, 16), blk>>>(memory, wv,  nullptr, v,           ROWS_X, DMODEL, DMODEL, 0);
    sgemm_kernel<<<dim3(8, 16), blk>>>(x,      wv,  nullptr, v + half,    ROWS_X, DMODEL, DMODEL, 0);

    // attention
    flash_kernel<<<dim3(16, HEADS, BATCH), blk, FLASH_SMEM>>>(q, ke, kr, v, u_bias, v_bias, av);

    // output proj + LN1
    sgemm_kernel<<<dim3(8, 16), blk>>>(av, wc, nullptr, tbuf, ROWS_X, DMODEL, DMODEL, 0);
    ln_kernel<<<ROWS_X, blk>>>(tbuf, x, ln1g, ln1b, ubuf);

    // FFN + LN2
    sgemm_kernel<<<dim3(32, 16), blk>>>(ubuf, w1, w1b, h1,   ROWS_X, FFDIM, DMODEL, 1);
    sgemm_kernel<<<dim3(8, 16),  blk>>>(h1,   w2, w2b, tbuf, ROWS_X, DMODEL, FFDIM, 0);
    ln_kernel<<<ROWS_X, blk>>>(tbuf, ubuf, ln2g, ln2b, out);
}

// round 2
// speedup vs baseline: 2.6272x; 2.6272x over previous
#include <cuda_runtime.h>
#include <cuda_bf16.h>
#include <math.h>
#include <stdint.h>

// Problem constants
#define S_LEN 1024
#define BATCH 2
#define DMODEL 1024
#define HEADS 16
#define HDIM 64
#define TLEN 2048
#define FFDIM 4096
#define ROWS_X (S_LEN * BATCH)     // 2048
#define ROWS_T (TLEN * BATCH)      // 4096

// ---------------- scratch buffers (device globals; no allocation allowed) ----
__device__ float g_q [ROWS_X * DMODEL];
__device__ float g_ke[ROWS_T * DMODEL];
__device__ float g_kr[ROWS_T * DMODEL];
__device__ float g_v [ROWS_T * DMODEL];
__device__ float g_av[ROWS_X * DMODEL];
__device__ float g_t [ROWS_X * DMODEL];
__device__ float g_u [ROWS_X * DMODEL];
__device__ float g_h1[ROWS_X * FFDIM];

// ---------------- tf32 tensor-core GEMM -------------------------------------
// C[M,N] = A[M,Kd] * W[N,Kd]^T (+bias)(+relu), blockIdx.z selects (W,C) pair.
// BM=BN=128, BK=32, 256 thr (8 warps, 2m x 4n), warp tile 64x32, mma m16n8k8.
// Double-buffered cp.async, XOR-swizzled smem (no pad), fp32 accum.

__device__ __forceinline__ uint32_t f2tf32(float f) {
    uint32_t r;
    asm("cvt.rna.tf32.f32 %0, %1;" : "=r"(r) : "f"(f));
    return r;
}

__device__ __forceinline__ void cp_async16(uint32_t saddr, const void* gptr) {
    asm volatile("cp.async.cg.shared.global [%0], [%1], 16;\n"
                 :: "r"(saddr), "l"(gptr));
}
__device__ __forceinline__ void cp_commit() {
    asm volatile("cp.async.commit_group;\n");
}
template <int N>
__device__ __forceinline__ void cp_wait() {
    asm volatile("cp.async.wait_group %0;\n" :: "n"(N));
}

__device__ __forceinline__ void mma_tf32(float* d, const uint32_t* a, const uint32_t* b) {
    asm volatile(
        "mma.sync.aligned.m16n8k8.row.col.f32.tf32.tf32.f32 "
        "{%0,%1,%2,%3}, {%4,%5,%6,%7}, {%8,%9}, {%0,%1,%2,%3};\n"
        : "+f"(d[0]), "+f"(d[1]), "+f"(d[2]), "+f"(d[3])
        : "r"(a[0]), "r"(a[1]), "r"(a[2]), "r"(a[3]), "r"(b[0]), "r"(b[1]));
}

// swizzled index for element (row, c) in a 128x32 float tile
__device__ __forceinline__ int sw_idx(int row, int c) {
    return (row << 5) + ((((c >> 2) ^ row) & 7) << 2) + (c & 3);
}

#define GEMM_SMEM (2 * 2 * 128 * 32 * 4)   // 65536 bytes

__global__ void __launch_bounds__(256)
tf32gemm_kernel(const float* __restrict__ A,
                const float* __restrict__ W0, const float* __restrict__ W1,
                const float* __restrict__ W2,
                const float* __restrict__ bias,
                float* __restrict__ C0, float* __restrict__ C1,
                float* __restrict__ C2,
                int M, int N, int Kd, int act)
{
    extern __shared__ float smem[];   // [stage][As 4096 | Ws 4096]

    const float* W = (blockIdx.z == 0) ? W0 : (blockIdx.z == 1 ? W1 : W2);
    float*       C = (blockIdx.z == 0) ? C0 : (blockIdx.z == 1 ? C1 : C2);

    const int tid = threadIdx.x;
    const int lane = tid & 31, wrp = tid >> 5;
    const int wm = wrp & 1;          // 0..1
    const int wn = wrp >> 1;         // 0..3
    const int q = lane >> 2, r = lane & 3;
    const int m0 = blockIdx.y * 128;
    const int n0 = blockIdx.x * 128;

    const int lrow = tid >> 3;       // 0..31
    const int lb   = tid & 7;        // float4 block 0..7

    float acc[4][4][4];
#pragma unroll
    for (int i = 0; i < 4; i++)
#pragma unroll
        for (int j = 0; j < 4; j++)
#pragma unroll
            for (int e = 0; e < 4; e++) acc[i][j][e] = 0.f;

    uint32_t sbase = (uint32_t)__cvta_generic_to_shared(smem);

    // issue one stage of cp.async loads
    auto issue = [&](int buf, int k0) {
        uint32_t so = sbase + (uint32_t)buf * 8192u * 4u;
#pragma unroll
        for (int i = 0; i < 4; i++) {
            int row = lrow + i * 32;
            int sidx = (row << 5) + (((lb ^ (row & 7))) << 2);
            cp_async16(so + sidx * 4, A + (size_t)(m0 + row) * Kd + k0 + lb * 4);
            cp_async16(so + (4096 + sidx) * 4, W + (size_t)(n0 + row) * Kd + k0 + lb * 4);
        }
    };

    const int KT = Kd >> 5;
    issue(0, 0);
    cp_commit();

    for (int kt = 0; kt < KT; kt++) {
        const int cur = kt & 1;
        if (kt + 1 < KT) {
            issue(cur ^ 1, (kt + 1) << 5);
            cp_commit();
            cp_wait<1>();
        } else {
            cp_wait<0>();
        }
        __syncthreads();

        const float* As = smem + (size_t)cur * 8192;
        const float* Ws = As + 4096;

#pragma unroll
        for (int kk = 0; kk < 32; kk += 8) {
            uint32_t afr[4][4];
#pragma unroll
            for (int mt = 0; mt < 4; mt++) {
                int mr = wm * 64 + mt * 16 + q;
                afr[mt][0] = f2tf32(As[sw_idx(mr,     kk + r)]);
                afr[mt][1] = f2tf32(As[sw_idx(mr + 8, kk + r)]);
                afr[mt][2] = f2tf32(As[sw_idx(mr,     kk + 4 + r)]);
                afr[mt][3] = f2tf32(As[sw_idx(mr + 8, kk + 4 + r)]);
            }
            uint32_t bfr[4][2];
#pragma unroll
            for (int nt = 0; nt < 4; nt++) {
                int nr = wn * 32 + nt * 8 + q;
                bfr[nt][0] = f2tf32(Ws[sw_idx(nr, kk + r)]);
                bfr[nt][1] = f2tf32(Ws[sw_idx(nr, kk + 4 + r)]);
            }
#pragma unroll
            for (int mt = 0; mt < 4; mt++)
#pragma unroll
                for (int nt = 0; nt < 4; nt++)
                    mma_tf32(acc[mt][nt], afr[mt], bfr[nt]);
        }
        __syncthreads();
    }

    // epilogue
#pragma unroll
    for (int mt = 0; mt < 4; mt++) {
        int row0 = m0 + wm * 64 + mt * 16 + q;
#pragma unroll
        for (int nt = 0; nt < 4; nt++) {
            int col = n0 + wn * 32 + nt * 8 + r * 2;
            float b0 = bias ? bias[col]     : 0.f;
            float b1 = bias ? bias[col + 1] : 0.f;
            float v0 = acc[mt][nt][0] + b0, v1 = acc[mt][nt][1] + b1;
            float v2 = acc[mt][nt][2] + b0, v3 = acc[mt][nt][3] + b1;
            if (act == 1) {
                v0 = fmaxf(v0, 0.f); v1 = fmaxf(v1, 0.f);
                v2 = fmaxf(v2, 0.f); v3 = fmaxf(v3, 0.f);
            }
            *(float2*)(C + (size_t)row0 * N + col)       = make_float2(v0, v1);
            *(float2*)(C + (size_t)(row0 + 8) * N + col) = make_float2(v2, v3);
        }
    }
}

// ---------------- Flash attention with fused-KK trick ------------------------
#define FPAD 66
#define FLASH_SMEM ((4 * 64 * FPAD + 64 + 128) * 4)

__global__ void __launch_bounds__(256)
flash_kernel(const float* __restrict__ q, const float* __restrict__ ke,
             const float* __restrict__ kr, const float* __restrict__ v,
             const float* __restrict__ ub, const float* __restrict__ vb,
             float* __restrict__ out)
{
    extern __shared__ float sm[];
    float* Qt   = sm;                    // [64][66]  Q^T : Qt[d][s]
    float* KKt  = Qt  + 64 * FPAD;       // [64][66]  (ke+kr)^T
    float* Vs   = KKt + 64 * FPAD;       // [64][66]  V[t][d]
    float* St   = Vs  + 64 * FPAD;       // [64][66]  P^T
    float* biasT = St + 64 * FPAD;       // [64]
    float* ubs  = biasT + 64;            // [64]
    float* vbs  = ubs + 64;              // [64]

    const int qb = blockIdx.x, h = blockIdx.y, b = blockIdx.z;
    const int tid = threadIdx.x;
    const int tx = tid & 15, ty = tid >> 4;
    const int lane = tid & 31, wrp = tid >> 5;

    if (tid < 64)       ubs[tid]      = ub[h * 64 + tid];
    else if (tid < 128) vbs[tid - 64] = vb[h * 64 + (tid - 64)];

#pragma unroll
    for (int it = 0; it < 4; it++) {
        int idx = tid + it * 256;
        int s = idx >> 4, d4 = (idx & 15) * 4;
        float4 qv = *(const float4*)(q + ((size_t)((qb * 64 + s) * BATCH + b)) * DMODEL + h * 64 + d4);
        Qt[(d4 + 0) * FPAD + s] = qv.x;
        Qt[(d4 + 1) * FPAD + s] = qv.y;
        Qt[(d4 + 2) * FPAD + s] = qv.z;
        Qt[(d4 + 3) * FPAD + s] = qv.w;
    }

    float m_i[4], l_i[4], O[4][4];
#pragma unroll
    for (int i = 0; i < 4; i++) {
        m_i[i] = -1e30f; l_i[i] = 0.f;
#pragma unroll
        for (int j = 0; j < 4; j++) O[i][j] = 0.f;
    }

    const int ntiles = 17 + qb;
    for (int tt = 0; tt < ntiles; tt++) {
        const int t0 = tt * 64;

#pragma unroll
        for (int rr = 0; rr < 8; rr++) {
            int t = wrp * 8 + rr;
            size_t base = ((size_t)((t0 + t) * BATCH + b)) * DMODEL + h * 64;
            float2 kev = *(const float2*)(ke + base + lane * 2);
            float2 krv = *(const float2*)(kr + base + lane * 2);
            KKt[(lane * 2 + 0) * FPAD + t] = kev.x + krv.x;
            KKt[(lane * 2 + 1) * FPAD + t] = kev.y + krv.y;
            float bsum = ubs[lane * 2] * kev.x + ubs[lane * 2 + 1] * kev.y
                       + vbs[lane * 2] * krv.x + vbs[lane * 2 + 1] * krv.y;
#pragma unroll
            for (int off = 16; off; off >>= 1)
                bsum += __shfl_xor_sync(0xffffffffu, bsum, off);
            if (lane == 0) biasT[t] = bsum;
        }
#pragma unroll
        for (int it = 0; it < 4; it++) {
            int idx = tid + it * 256;
            int t = idx >> 4, d4 = (idx & 15) * 4;
            float4 vv = *(const float4*)(v + ((size_t)((t0 + t) * BATCH + b)) * DMODEL + h * 64 + d4);
            Vs[t * FPAD + d4 + 0] = vv.x;
            Vs[t * FPAD + d4 + 1] = vv.y;
            Vs[t * FPAD + d4 + 2] = vv.z;
            Vs[t * FPAD + d4 + 3] = vv.w;
        }
        __syncthreads();

        float sc[4][4];
#pragma unroll
        for (int i = 0; i < 4; i++)
#pragma unroll
            for (int j = 0; j < 4; j++) sc[i][j] = 0.f;

#pragma unroll 8
        for (int d = 0; d < 64; d++) {
            float a[4], bb[4];
            float2 qa = *(const float2*)&Qt[d * FPAD + ty * 4];
            float2 qc = *(const float2*)&Qt[d * FPAD + ty * 4 + 2];
            float2 ka = *(const float2*)&KKt[d * FPAD + tx * 4];
            float2 kc = *(const float2*)&KKt[d * FPAD + tx * 4 + 2];
            a[0] = qa.x; a[1] = qa.y; a[2] = qc.x; a[3] = qc.y;
            bb[0] = ka.x; bb[1] = ka.y; bb[2] = kc.x; bb[3] = kc.y;
#pragma unroll
            for (int i = 0; i < 4; i++)
#pragma unroll
                for (int j = 0; j < 4; j++)
                    sc[i][j] = fmaf(a[i], bb[j], sc[i][j]);
        }

        const bool diag = (tt == 16 + qb);
#pragma unroll
        for (int j = 0; j < 4; j++) {
            float bj = biasT[tx * 4 + j];
#pragma unroll
            for (int i = 0; i < 4; i++) {
                float vv = (sc[i][j] + bj) * 0.125f;
                if (diag && (tx * 4 + j) > (ty * 4 + i)) vv = -1e30f;
                sc[i][j] = vv;
            }
        }

#pragma unroll
        for (int i = 0; i < 4; i++) {
            float mt = fmaxf(fmaxf(sc[i][0], sc[i][1]), fmaxf(sc[i][2], sc[i][3]));
#pragma unroll
            for (int off = 8; off; off >>= 1)
                mt = fmaxf(mt, __shfl_xor_sync(0xffffffffu, mt, off, 16));
            float mnew = fmaxf(m_i[i], mt);
            float c = __expf(m_i[i] - mnew);
            l_i[i] *= c;
#pragma unroll
            for (int j = 0; j < 4; j++) O[i][j] *= c;
            float ps = 0.f;
#pragma unroll
            for (int j = 0; j < 4; j++) {
                float pv = __expf(sc[i][j] - mnew);
                sc[i][j] = pv;
                ps += pv;
            }
            l_i[i] += ps;
            m_i[i] = mnew;
        }
#pragma unroll
        for (int i = 0; i < 4; i++)
#pragma unroll
            for (int j = 0; j < 4; j++)
                St[(tx * 4 + j) * FPAD + ty * 4 + i] = sc[i][j];
        __syncthreads();

#pragma unroll 8
        for (int t = 0; t < 64; t++) {
            float a[4], bb[4];
            float2 pa = *(const float2*)&St[t * FPAD + ty * 4];
            float2 pc = *(const float2*)&St[t * FPAD + ty * 4 + 2];
            float2 va = *(const float2*)&Vs[t * FPAD + tx * 4];
            float2 vc = *(const float2*)&Vs[t * FPAD + tx * 4 + 2];
            a[0] = pa.x; a[1] = pa.y; a[2] = pc.x; a[3] = pc.y;
            bb[0] = va.x; bb[1] = va.y; bb[2] = vc.x; bb[3] = vc.y;
#pragma unroll
            for (int i = 0; i < 4; i++)
#pragma unroll
                for (int j = 0; j < 4; j++)
                    O[i][j] = fmaf(a[i], bb[j], O[i][j]);
        }
        __syncthreads();
    }

#pragma unroll
    for (int i = 0; i < 4; i++) {
        float lt = l_i[i];
#pragma unroll
        for (int off = 8; off; off >>= 1)
            lt += __shfl_xor_sync(0xffffffffu, lt, off, 16);
        float inv = 1.f / lt;
        int s = qb * 64 + ty * 4 + i;
        float* orow = out + ((size_t)(s * BATCH + b)) * DMODEL + h * 64 + tx * 4;
#pragma unroll
        for (int j = 0; j < 4; j++) orow[j] = O[i][j] * inv;
    }
}

// ---------------- LayerNorm(a + res) * g + b --------------------------------
__global__ void __launch_bounds__(256)
ln_kernel(const float* __restrict__ a, const float* __restrict__ res,
          const float* __restrict__ g, const float* __restrict__ bta,
          float* __restrict__ out)
{
    const int row = blockIdx.x;
    const int tid = threadIdx.x;
    const int lane = tid & 31, wrp = tid >> 5;
    __shared__ float red[8];
    __shared__ float bc;

    float vals[4];
    float s = 0.f;
    const float* ar = a + (size_t)row * DMODEL;
    const float* rr = res + (size_t)row * DMODEL;
#pragma unroll
    for (int i = 0; i < 4; i++) {
        int d = tid + i * 256;
        vals[i] = ar[d] + rr[d];
        s += vals[i];
    }
#pragma unroll
    for (int off = 16; off; off >>= 1) s += __shfl_xor_sync(0xffffffffu, s, off);
    if (lane == 0) red[wrp] = s;
    __syncthreads();
    if (tid == 0) {
        float t = 0.f;
#pragma unroll
        for (int w = 0; w < 8; w++) t += red[w];
        bc = t * (1.f / DMODEL);
    }
    __syncthreads();
    const float mu = bc;

    float vs = 0.f;
#pragma unroll
    for (int i = 0; i < 4; i++) {
        float dd = vals[i] - mu;
        vs += dd * dd;
    }
#pragma unroll
    for (int off = 16; off; off >>= 1) vs += __shfl_xor_sync(0xffffffffu, vs, off);
    __syncthreads();
    if (lane == 0) red[wrp] = vs;
    __syncthreads();
    if (tid == 0) {
        float t = 0.f;
#pragma unroll
        for (int w = 0; w < 8; w++) t += red[w];
        bc = rsqrtf(t * (1.f / DMODEL) + 1e-5f);
    }
    __syncthreads();
    const float rstd = bc;

    float* orow = out + (size_t)row * DMODEL;
#pragma unroll
    for (int i = 0; i < 4; i++) {
        int d = tid + i * 256;
        orow[d] = (vals[i] - mu) * rstd * g[d] + bta[d];
    }
}

// ---------------- launcher ---------------------------------------------------
extern "C" void kernel_launch(void* const* d_in, const int* in_sizes, int n_in,
                              void* d_out, int out_size)
{
    const float* x      = (const float*)d_in[0];
    const float* p      = (const float*)d_in[1];
    /* mask d_in[2] is analytic: unused */
    const float* memory = (const float*)d_in[3];
    const float* u_bias = (const float*)d_in[4];
    const float* v_bias = (const float*)d_in[5];
    const float* wq  = (const float*)d_in[6];
    const float* wke = (const float*)d_in[7];
    const float* wkr = (const float*)d_in[8];
    const float* wv  = (const float*)d_in[9];
    const float* wc  = (const float*)d_in[10];
    const float* w1  = (const float*)d_in[11];
    const float* w1b = (const float*)d_in[12];
    const float* w2  = (const float*)d_in[13];
    const float* w2b = (const float*)d_in[14];
    const float* ln1g = (const float*)d_in[15];
    const float* ln1b = (const float*)d_in[16];
    const float* ln2g = (const float*)d_in[17];
    const float* ln2b = (const float*)d_in[18];
    float* out = (float*)d_out;

    float *q, *ke, *kr, *v, *av, *tbuf, *ubuf, *h1;
    cudaGetSymbolAddress((void**)&q,    g_q);
    cudaGetSymbolAddress((void**)&ke,   g_ke);
    cudaGetSymbolAddress((void**)&kr,   g_kr);
    cudaGetSymbolAddress((void**)&v,    g_v);
    cudaGetSymbolAddress((void**)&av,   g_av);
    cudaGetSymbolAddress((void**)&tbuf, g_t);
    cudaGetSymbolAddress((void**)&ubuf, g_u);
    cudaGetSymbolAddress((void**)&h1,   g_h1);

    cudaFuncSetAttribute(tf32gemm_kernel,
                         cudaFuncAttributeMaxDynamicSharedMemorySize, GEMM_SMEM);
    cudaFuncSetAttribute(flash_kernel,
                         cudaFuncAttributeMaxDynamicSharedMemorySize, FLASH_SMEM);

    const dim3 blk(256);
    const size_t half = (size_t)ROWS_X * DMODEL;

    // batched projections from x: q, ke (second half), v (second half)
    tf32gemm_kernel<<<dim3(8, 16, 3), blk, GEMM_SMEM>>>(
        x, wq, wke, wv, nullptr, q, ke + half, v + half,
        ROWS_X, DMODEL, DMODEL, 0);
    // batched projections from memory: ke (first half), v (first half)
    tf32gemm_kernel<<<dim3(8, 16, 2), blk, GEMM_SMEM>>>(
        memory, wke, wv, nullptr, nullptr, ke, v, nullptr,
        ROWS_X, DMODEL, DMODEL, 0);
    // relative-position keys from p
    tf32gemm_kernel<<<dim3(8, 32, 1), blk, GEMM_SMEM>>>(
        p, wkr, nullptr, nullptr, nullptr, kr, nullptr, nullptr,
        ROWS_T, DMODEL, DMODEL, 0);

    // attention
    flash_kernel<<<dim3(16, HEADS, BATCH), blk, FLASH_SMEM>>>(q, ke, kr, v, u_bias, v_bias, av);

    // output proj + LN1
    tf32gemm_kernel<<<dim3(8, 16, 1), blk, GEMM_SMEM>>>(
        av, wc, nullptr, nullptr, nullptr, tbuf, nullptr, nullptr,
        ROWS_X, DMODEL, DMODEL, 0);
    ln_kernel<<<ROWS_X, blk>>>(tbuf, x, ln1g, ln1b, ubuf);

    // FFN + LN2
    tf32gemm_kernel<<<dim3(32, 16, 1), blk, GEMM_SMEM>>>(
        ubuf, w1, nullptr, nullptr, w1b, h1, nullptr, nullptr,
        ROWS_X, FFDIM, DMODEL, 1);
    tf32gemm_kernel<<<dim3(8, 16, 1), blk, GEMM_SMEM>>>(
        h1, w2, nullptr, nullptr, w2b, tbuf, nullptr, nullptr,
        ROWS_X, DMODEL, FFDIM, 0);
    ln_kernel<<<ROWS_X, blk>>>(tbuf, ubuf, ln2g, ln2b, out);
}